// round 14
// baseline (speedup 1.0000x reference)
#include <cuda_runtime.h>
#include <cuda_bf16.h>
#include <cuda_fp16.h>
#include <cstdint>

#define B_   2
#define S_   2048
#define E_   1024
#define H_   16
#define D_   64
#define BH_  (B_*H_)      // 32
#define TOK_ (B_*S_)      // 4096

// single dynamic-smem symbol shared by all kernels
extern __shared__ __align__(16) char dynsm[];

// ===========================================================================
// helpers
// ===========================================================================
__device__ __forceinline__ uint32_t smem_u32(const void* p) {
    uint32_t a;
    asm("{ .reg .u64 t; cvta.to.shared.u64 t, %1; cvt.u32.u64 %0, t; }" : "=r"(a) : "l"(p));
    return a;
}
#define CP_COMMIT()  asm volatile("cp.async.commit_group;" ::: "memory")
#define CP_WAIT0()   asm volatile("cp.async.wait_group 0;" ::: "memory")
#define CP_WAIT1()   asm volatile("cp.async.wait_group 1;" ::: "memory")

__device__ __forceinline__ void cp16(uint32_t dst, const void* src) {
    asm volatile("cp.async.cg.shared.global [%0], [%1], 16;" :: "r"(dst), "l"(src) : "memory");
}

// m16n8k16 bf16 MMA, fp32 accum. A row-major, B col-major ([n][k] row-major).
__device__ __forceinline__ void mma_bf16(float c[4], const uint32_t a[4], const uint32_t b[2]) {
    asm volatile("mma.sync.aligned.m16n8k16.row.col.f32.bf16.bf16.f32 "
        "{%0,%1,%2,%3}, {%4,%5,%6,%7}, {%8,%9}, {%0,%1,%2,%3};"
        : "+f"(c[0]), "+f"(c[1]), "+f"(c[2]), "+f"(c[3])
        : "r"(a[0]), "r"(a[1]), "r"(a[2]), "r"(a[3]), "r"(b[0]), "r"(b[1]));
}
// m16n8k16 fp16 MMA, fp32 accum.
__device__ __forceinline__ void mma_f16(float c[4], const uint32_t a[4], const uint32_t b[2]) {
    asm volatile("mma.sync.aligned.m16n8k16.row.col.f32.f16.f16.f32 "
        "{%0,%1,%2,%3}, {%4,%5,%6,%7}, {%8,%9}, {%0,%1,%2,%3};"
        : "+f"(c[0]), "+f"(c[1]), "+f"(c[2]), "+f"(c[3])
        : "r"(a[0]), "r"(a[1]), "r"(a[2]), "r"(a[3]), "r"(b[0]), "r"(b[1]));
}

__device__ __forceinline__ void split2(float v, __nv_bfloat16& h, __nv_bfloat16& l) {
    h = __float2bfloat16(v);
    l = __float2bfloat16(v - __bfloat162float(h));
}

// A-fragment from a row-major smem tile (stride bytes), rows r0/r0+8, k-bytes kb
__device__ __forceinline__ void lda4(uint32_t a[4], const char* t, int stride, int r0, int kb) {
    a[0] = *(const uint32_t*)(t + (size_t)(r0    )*stride + kb);
    a[1] = *(const uint32_t*)(t + (size_t)(r0 + 8)*stride + kb);
    a[2] = *(const uint32_t*)(t + (size_t)(r0    )*stride + kb + 16);
    a[3] = *(const uint32_t*)(t + (size_t)(r0 + 8)*stride + kb + 16);
}
// B-fragment from [n][k] row-major tile
__device__ __forceinline__ void ldb2(uint32_t b[2], const char* t, int stride, int n, int kb) {
    b[0] = *(const uint32_t*)(t + (size_t)n*stride + kb);
    b[1] = *(const uint32_t*)(t + (size_t)n*stride + kb + 16);
}

// load [rows x 32] 16-bit-elem chunk -> smem rows of 80 bytes (64 B + 16 pad)
__device__ __forceinline__ void ld_chunk32(char* s, const void* g, int ld, int rows) {
    uint32_t sb = smem_u32(s);
    const char* gb = (const char*)g;
    for (int i = threadIdx.x; i < rows*4; i += 256) {
        int r = i >> 2, c = i & 3;
        cp16(sb + r*80 + c*16, gb + (size_t)r*ld*2 + c*16);
    }
}
// load [rows x 64] 16-bit-elem chunk -> smem rows of 144 bytes (128 B + 16 pad)
__device__ __forceinline__ void ld_chunk64(char* s, const void* g, int ld, int rows) {
    uint32_t sb = smem_u32(s);
    const char* gb = (const char*)g;
    for (int i = threadIdx.x; i < rows*8; i += 256) {
        int r = i >> 3, c = i & 7;
        cp16(sb + r*144 + c*16, gb + (size_t)r*ld*2 + c*16);
    }
}

// ===========================================================================
// static device scratch
// ===========================================================================
__device__ __half         d_Es[BH_*(size_t)S_*S_];        // 268 MB fp16 exp(s-4)
__device__ __half         d_Pf[BH_*(size_t)S_*S_];        // 268 MB fp16 P
__device__ float          d_psums[BH_*(size_t)S_*32];     // 8 MB per-row partial exp-sums
__device__ __nv_bfloat16  d_X3h[3*TOK_*E_], d_X3l[3*TOK_*E_];  // q/k/v inputs split
__device__ __nv_bfloat16  d_W3h[3*E_*E_],  d_W3l[3*E_*E_];     // Wq/Wk/Wv^T split
__device__ __nv_bfloat16  d_Wth[E_*E_],  d_Wtl[E_*E_];         // Wo^T split
__device__ __half         d_Qf[BH_*S_*D_];                     // fp16 Q
__device__ __half         d_Kf[BH_*S_*D_];                     // fp16 K
__device__ __half         d_Vf[BH_*S_*D_];                     // fp16 V
__device__ __nv_bfloat16  d_Ch[TOK_*E_],  d_Cl[TOK_*E_];       // ctx split [B,S,E]
__device__ float          d_mixsm[H_*H_];

// ===========================================================================
// 0) softmax of the 16x16 head-mixing matrix
// ===========================================================================
__global__ void mix_softmax_kernel(const float* __restrict__ hm) {
    int g = threadIdx.x;
    if (g >= H_) return;
    float m = -1e30f;
    #pragma unroll
    for (int h = 0; h < H_; h++) m = fmaxf(m, hm[g*H_ + h]);
    float e[H_]; float s = 0.f;
    #pragma unroll
    for (int h = 0; h < H_; h++) { e[h] = expf(hm[g*H_ + h] - m); s += e[h]; }
    float inv = 1.f / s;
    #pragma unroll
    for (int h = 0; h < H_; h++) d_mixsm[g*H_ + h] = e[h] * inv;
}

// ===========================================================================
// 1) fp32 -> split-bf16, 3 tensors in one launch (z selects)
// ===========================================================================
__global__ __launch_bounds__(256) void split_f3(const float* __restrict__ q,
        const float* __restrict__ k, const float* __restrict__ v, int n4) {
    int z = blockIdx.z;
    const float* in = (z == 0) ? q : (z == 1) ? k : v;
    __nv_bfloat16* oh = d_X3h + (size_t)z*TOK_*E_;
    __nv_bfloat16* ol = d_X3l + (size_t)z*TOK_*E_;
    int i = blockIdx.x*256 + threadIdx.x;
    if (i >= n4) return;
    float4 vv = ((const float4*)in)[i];
    __nv_bfloat16 h0,h1,h2,h3,l0,l1,l2,l3;
    split2(vv.x,h0,l0); split2(vv.y,h1,l1); split2(vv.z,h2,l2); split2(vv.w,h3,l3);
    __nv_bfloat162 p;
    p.x=h0; p.y=h1; ((__nv_bfloat162*)oh)[2*i]   = p;
    p.x=h2; p.y=h3; ((__nv_bfloat162*)oh)[2*i+1] = p;
    p.x=l0; p.y=l1; ((__nv_bfloat162*)ol)[2*i]   = p;
    p.x=l2; p.y=l3; ((__nv_bfloat162*)ol)[2*i+1] = p;
}

// ===========================================================================
// 2) W [K,N] fp32 -> W^T [N,K] split-bf16. wt3: 3 weights in one launch.
// ===========================================================================
__device__ __forceinline__ void wt_body(const float* __restrict__ W,
        __nv_bfloat16* __restrict__ oh, __nv_bfloat16* __restrict__ ol) {
    __shared__ float t[32][33];
    int n0 = blockIdx.x*32, k0 = blockIdx.y*32;
    int tx = threadIdx.x, ty = threadIdx.y;
    #pragma unroll
    for (int i = 0; i < 4; i++)
        t[ty+8*i][tx] = W[(size_t)(k0+ty+8*i)*E_ + n0+tx];
    __syncthreads();
    #pragma unroll
    for (int i = 0; i < 4; i++) {
        float v = t[tx][ty+8*i];
        size_t idx = (size_t)(n0+ty+8*i)*E_ + k0 + tx;
        __nv_bfloat16 hb, lb; split2(v, hb, lb);
        oh[idx] = hb; ol[idx] = lb;
    }
}
__global__ void split_wt3(const float* __restrict__ Wq,
        const float* __restrict__ Wk, const float* __restrict__ Wv) {
    int z = blockIdx.z;
    const float* W = (z == 0) ? Wq : (z == 1) ? Wk : Wv;
    wt_body(W, d_W3h + (size_t)z*E_*E_, d_W3l + (size_t)z*E_*E_);
}
__global__ void split_wt(const float* __restrict__ W) {
    wt_body(W, d_Wth, d_Wtl);
}

// ===========================================================================
// 3a) QKV projection GEMM, z in {0,1,2}. 128x128 block, 8 warps @ 32x64.
//     Computed split-bf16 (3-product, accurate); epilogue stores fp16
//     [B,H,S,D] for all of Q, K, V.
// ===========================================================================
#define PROJ_SMEM (2*4*10240)   // 81920
__global__ __launch_bounds__(256) void gemm_qkv(
    const float* __restrict__ bq, const float* __restrict__ bk,
    const float* __restrict__ bv)
{
    char* sm = dynsm;
    const int z = blockIdx.z;
    const float* bias = (z == 0) ? bq : (z == 1) ? bk : bv;
    __half* outP = (z == 0) ? d_Qf : (z == 1) ? d_Kf : d_Vf;
    const __nv_bfloat16* Ah_ = d_X3h + (size_t)z*TOK_*E_;
    const __nv_bfloat16* Al_ = d_X3l + (size_t)z*TOK_*E_;
    const __nv_bfloat16* Bh_ = d_W3h + (size_t)z*E_*E_;
    const __nv_bfloat16* Bl_ = d_W3l + (size_t)z*E_*E_;

    const int tid = threadIdx.x, lane = tid & 31, wid = tid >> 5;
    const int wm = wid >> 1, wn = wid & 1;
    const int g = lane >> 2, tg = lane & 3;
    const int bm = blockIdx.y*128, bn = blockIdx.x*128;

    float acc[2][8][4];
    #pragma unroll
    for (int i = 0; i < 2; i++)
        #pragma unroll
        for (int j = 0; j < 8; j++)
            #pragma unroll
            for (int q = 0; q < 4; q++) acc[i][j][q] = 0.f;

    const __nv_bfloat16* gT[4] = { Ah_ + (size_t)bm*E_, Al_ + (size_t)bm*E_,
                                   Bh_ + (size_t)bn*E_, Bl_ + (size_t)bn*E_ };
    #pragma unroll
    for (int t = 0; t < 4; t++) ld_chunk32(sm + t*10240, gT[t], E_, 128);
    CP_COMMIT();

    for (int c = 0; c < 32; c++) {
        if (c < 31) {
            int k0 = (c+1)*32;
            char* st = sm + ((c+1)&1)*40960;
            #pragma unroll
            for (int t = 0; t < 4; t++) ld_chunk32(st + t*10240, gT[t] + k0, E_, 128);
            CP_COMMIT(); CP_WAIT1();
        } else CP_WAIT0();
        __syncthreads();
        const char* st = sm + (c&1)*40960;
        #pragma unroll
        for (int ks = 0; ks < 2; ks++) {
            int kb = ks*32 + tg*4;
            uint32_t aH[2][4], aL[2][4], bH[8][2], bL[8][2];
            #pragma unroll
            for (int i = 0; i < 2; i++) {
                int r0 = wm*32 + i*16 + g;
                lda4(aH[i], st,          80, r0, kb);
                lda4(aL[i], st + 10240,  80, r0, kb);
            }
            #pragma unroll
            for (int j = 0; j < 8; j++) {
                int n = wn*64 + j*8 + g;
                ldb2(bH[j], st + 20480, 80, n, kb);
                ldb2(bL[j], st + 30720, 80, n, kb);
            }
            #pragma unroll
            for (int i = 0; i < 2; i++)
                #pragma unroll
                for (int j = 0; j < 8; j++) {
                    mma_bf16(acc[i][j], aH[i], bH[j]);
                    mma_bf16(acc[i][j], aH[i], bL[j]);
                    mma_bf16(acc[i][j], aL[i], bH[j]);
                }
        }
        __syncthreads();
    }

    #pragma unroll
    for (int j = 0; j < 8; j++) {
        int c = bn + wn*64 + j*8 + tg*2;
        float b0 = bias[c], b1 = bias[c+1];
        #pragma unroll
        for (int i = 0; i < 2; i++) {
            #pragma unroll
            for (int half = 0; half < 2; half++) {
                int r = bm + wm*32 + i*16 + g + half*8;
                float v0 = acc[i][j][half*2+0] + b0;
                float v1 = acc[i][j][half*2+1] + b1;
                int bb = r >> 11, s = r & (S_-1);
                int h = c >> 6,  d = c & 63;
                size_t idx = (((size_t)bb*H_ + h)*S_ + s)*D_ + d;
                *(__half2*)&outP[idx] = __floats2half2_rn(v0, v1);
            }
        }
    }
}

// ===========================================================================
// 3b) output projection GEMM: out[4096,1024] fp32 = C @ Wo^T + bo
// ===========================================================================
__global__ __launch_bounds__(256) void gemm_out(
    const float* __restrict__ bias, float* __restrict__ outF)
{
    char* sm = dynsm;
    const int tid = threadIdx.x, lane = tid & 31, wid = tid >> 5;
    const int wm = wid >> 1, wn = wid & 1;
    const int g = lane >> 2, tg = lane & 3;
    const int bm = blockIdx.y*128, bn = blockIdx.x*128;

    float acc[2][8][4];
    #pragma unroll
    for (int i = 0; i < 2; i++)
        #pragma unroll
        for (int j = 0; j < 8; j++)
            #pragma unroll
            for (int q = 0; q < 4; q++) acc[i][j][q] = 0.f;

    const __nv_bfloat16* gT[4] = { d_Ch + (size_t)bm*E_, d_Cl + (size_t)bm*E_,
                                   d_Wth + (size_t)bn*E_, d_Wtl + (size_t)bn*E_ };
    #pragma unroll
    for (int t = 0; t < 4; t++) ld_chunk32(sm + t*10240, gT[t], E_, 128);
    CP_COMMIT();

    for (int c = 0; c < 32; c++) {
        if (c < 31) {
            int k0 = (c+1)*32;
            char* st = sm + ((c+1)&1)*40960;
            #pragma unroll
            for (int t = 0; t < 4; t++) ld_chunk32(st + t*10240, gT[t] + k0, E_, 128);
            CP_COMMIT(); CP_WAIT1();
        } else CP_WAIT0();
        __syncthreads();
        const char* st = sm + (c&1)*40960;
        #pragma unroll
        for (int ks = 0; ks < 2; ks++) {
            int kb = ks*32 + tg*4;
            uint32_t aH[2][4], aL[2][4], bH[8][2], bL[8][2];
            #pragma unroll
            for (int i = 0; i < 2; i++) {
                int r0 = wm*32 + i*16 + g;
                lda4(aH[i], st,          80, r0, kb);
                lda4(aL[i], st + 10240,  80, r0, kb);
            }
            #pragma unroll
            for (int j = 0; j < 8; j++) {
                int n = wn*64 + j*8 + g;
                ldb2(bH[j], st + 20480, 80, n, kb);
                ldb2(bL[j], st + 30720, 80, n, kb);
            }
            #pragma unroll
            for (int i = 0; i < 2; i++)
                #pragma unroll
                for (int j = 0; j < 8; j++) {
                    mma_bf16(acc[i][j], aH[i], bH[j]);
                    mma_bf16(acc[i][j], aH[i], bL[j]);
                    mma_bf16(acc[i][j], aL[i], bH[j]);
                }
        }
        __syncthreads();
    }

    #pragma unroll
    for (int j = 0; j < 8; j++) {
        int c = bn + wn*64 + j*8 + tg*2;
        float b0 = bias[c], b1 = bias[c+1];
        #pragma unroll
        for (int i = 0; i < 2; i++) {
            #pragma unroll
            for (int half = 0; half < 2; half++) {
                int r = bm + wm*32 + i*16 + g + half*8;
                float2 f;
                f.x = acc[i][j][half*2+0] + b0;
                f.y = acc[i][j][half*2+1] + b1;
                *(float2*)&outF[(size_t)r*E_ + c] = f;
            }
        }
    }
}

// ===========================================================================
// 4) exp-scores: E = exp(Q K^T / 8 - 4) per (b,h), stored fp16, plus
//    deterministic per-row partial sums of exp values -> d_psums.
//    Single fp16 product; 128x128 block, K=64 single-shot.
// ===========================================================================
#define SC_SMEM (2*18432)   // 36864
__global__ __launch_bounds__(256) void scores_mma()
{
    char* sm = dynsm;
    const int tid = threadIdx.x, lane = tid & 31, wid = tid >> 5;
    const int wm = wid >> 1, wn = wid & 1;
    const int g = lane >> 2, tg = lane & 3;
    const int bh = blockIdx.z;
    const int bm = blockIdx.y*128, bn = blockIdx.x*128;

    ld_chunk64(sm,           d_Qf + (size_t)bh*S_*D_ + (size_t)bm*D_, D_, 128);
    ld_chunk64(sm + 18432,   d_Kf + (size_t)bh*S_*D_ + (size_t)bn*D_, D_, 128);
    CP_COMMIT(); CP_WAIT0();
    __syncthreads();

    float acc[2][8][4];
    #pragma unroll
    for (int i = 0; i < 2; i++)
        #pragma unroll
        for (int j = 0; j < 8; j++)
            #pragma unroll
            for (int q = 0; q < 4; q++) acc[i][j][q] = 0.f;

    #pragma unroll
    for (int ks = 0; ks < 4; ks++) {
        int kb = ks*32 + tg*4;
        uint32_t aF[2][4], bF[8][2];
        #pragma unroll
        for (int i = 0; i < 2; i++) {
            int r0 = wm*32 + i*16 + g;
            lda4(aF[i], sm, 144, r0, kb);
        }
        #pragma unroll
        for (int j = 0; j < 8; j++) {
            int n = wn*64 + j*8 + g;
            ldb2(bF[j], sm + 18432, 144, n, kb);
        }
        #pragma unroll
        for (int i = 0; i < 2; i++)
            #pragma unroll
            for (int j = 0; j < 8; j++)
                mma_f16(acc[i][j], aF[i], bF[j]);
    }

    __half* outb = d_Es + (size_t)bh*S_*S_;
    float rsum[2][2] = {{0.f, 0.f}, {0.f, 0.f}};
    #pragma unroll
    for (int i = 0; i < 2; i++)
        #pragma unroll
        for (int j = 0; j < 8; j++) {
            int c = bn + wn*64 + j*8 + tg*2;
            #pragma unroll
            for (int half = 0; half < 2; half++) {
                int r = bm + wm*32 + i*16 + g + half*8;
                float e0 = __expf(acc[i][j][half*2+0] * 0.125f - 4.f);
                float e1 = __expf(acc[i][j][half*2+1] * 0.125f - 4.f);
                *(__half2*)&outb[(size_t)r*S_ + c] = __floats2half2_rn(e0, e1);
                rsum[i][half] += e0 + e1;
            }
        }

    // quad-reduce over tg (columns), one deterministic partial per (row, tile, wn)
    #pragma unroll
    for (int i = 0; i < 2; i++)
        #pragma unroll
        for (int half = 0; half < 2; half++) {
            float v = rsum[i][half];
            v += __shfl_xor_sync(0xFFFFFFFFu, v, 1);
            v += __shfl_xor_sync(0xFFFFFFFFu, v, 2);
            if (tg == 0) {
                int r = bm + wm*32 + i*16 + g + half*8;
                d_psums[((size_t)bh*S_ + r)*32 + blockIdx.x*2 + wn] = v;
            }
        }
}

// ===========================================================================
// 5) streaming normalize + head mixing. Block per (b,q), 256 threads,
//    NO dynamic smem (high occupancy). inv from d_psums; emits fp16 P.
// ===========================================================================
__global__ __launch_bounds__(256) void softmax_mix_kernel()
{
    __shared__ float sinv[16];
    __shared__ float mixs[256];
    const int bq = blockIdx.x;
    const int b = bq >> 11, q = bq & (S_-1);
    const int tid = threadIdx.x;

    mixs[tid] = d_mixsm[tid];
    if (tid < 16) {
        const float* p = d_psums + ((size_t)(b*H_ + tid)*S_ + q)*32;
        float s = 0.f;
        #pragma unroll
        for (int t = 0; t < 32; t++) s += p[t];
        sinv[tid] = 1.f / s;
    }
    __syncthreads();

    const __half* src = d_Es + ((size_t)b*H_)*S_*S_ + (size_t)q*S_;
    __half*       dst = d_Pf + ((size_t)b*H_)*S_*S_ + (size_t)q*S_;
    for (int k2 = tid; k2 < S_/2; k2 += 256) {
        float a0[H_], a1[H_];
        #pragma unroll
        for (int h = 0; h < H_; h++) {
            __half2 e = *(const __half2*)(src + (size_t)h*S_*S_ + k2*2);
            float2 f = __half22float2(e);
            a0[h] = f.x * sinv[h];
            a1[h] = f.y * sinv[h];
        }
        #pragma unroll
        for (int g = 0; g < H_; g++) {
            float o0 = 0.f, o1 = 0.f;
            #pragma unroll
            for (int h = 0; h < H_; h++) {
                o0 = fmaf(mixs[g*16 + h], a0[h], o0);
                o1 = fmaf(mixs[g*16 + h], a1[h], o1);
            }
            *(__half2*)(dst + (size_t)g*S_*S_ + k2*2) = __floats2half2_rn(o0, o1);
        }
    }
}

// ===========================================================================
// 6) ctx = P @ V per (b,g), fp16 single-product. 128x64 block, 8 warps.
// ===========================================================================
#define CTX_STAGE (10240 + 4608)          // 14848
#define CTX_SMEM  (2*CTX_STAGE)           // 29696
__global__ __launch_bounds__(256) void ctx_mma()
{
    char* sm = dynsm;
    const int tid = threadIdx.x, lane = tid & 31, wid = tid >> 5;
    const int wm = wid >> 1, wn = wid & 1;
    const int g = lane >> 2, tg = lane & 3;
    const int bg = blockIdx.y;
    const int b = bg >> 4, ghead = bg & 15;
    const int bm = blockIdx.x*128;

    const __half* pf = d_Pf + (size_t)bg*S_*S_ + (size_t)bm*S_;
    const __half* vf = d_Vf + (size_t)bg*S_*D_;

    float acc[2][4][4];
    #pragma unroll
    for (int i = 0; i < 2; i++)
        #pragma unroll
        for (int j = 0; j < 4; j++)
            #pragma unroll
            for (int q = 0; q < 4; q++) acc[i][j][q] = 0.f;

    {   // preload chunk 0
        char* st = sm;
        ld_chunk32(st,         pf, S_, 128);
        ld_chunk64(st + 10240, vf, D_, 32);
        CP_COMMIT();
    }
    for (int c = 0; c < 64; c++) {
        if (c < 63) {
            int k0 = (c+1)*32;
            char* st = sm + ((c+1)&1)*CTX_STAGE;
            ld_chunk32(st,         pf + k0, S_, 128);
            ld_chunk64(st + 10240, vf + (size_t)k0*D_, D_, 32);
            CP_COMMIT(); CP_WAIT1();
        } else CP_WAIT0();
        __syncthreads();
        const char* st = sm + (c&1)*CTX_STAGE;
        const char* vF = st + 10240;
        #pragma unroll
        for (int ks = 0; ks < 2; ks++) {
            int kb = ks*32 + tg*4;
            uint32_t aF[2][4], bF[4][2];
            #pragma unroll
            for (int i = 0; i < 2; i++) {
                int r0 = wm*32 + i*16 + g;
                lda4(aF[i], st, 80, r0, kb);
            }
            int krow = ks*16 + tg*2;
            #pragma unroll
            for (int j = 0; j < 4; j++) {
                int n2 = (wn*32 + j*8 + g)*2;
                uint32_t x0, x1, x2, x3;
                x0 = *(const unsigned short*)(vF + (krow  )*144 + n2);
                x1 = *(const unsigned short*)(vF + (krow+1)*144 + n2);
                x2 = *(const unsigned short*)(vF + (krow+8)*144 + n2);
                x3 = *(const unsigned short*)(vF + (krow+9)*144 + n2);
                bF[j][0] = x0 | (x1 << 16);
                bF[j][1] = x2 | (x3 << 16);
            }
            #pragma unroll
            for (int i = 0; i < 2; i++)
                #pragma unroll
                for (int j = 0; j < 4; j++)
                    mma_f16(acc[i][j], aF[i], bF[j]);
        }
        __syncthreads();
    }

    #pragma unroll
    for (int i = 0; i < 2; i++)
        #pragma unroll
        for (int j = 0; j < 4; j++) {
            int d = wn*32 + j*8 + tg*2;
            #pragma unroll
            for (int half = 0; half < 2; half++) {
                int q = bm + wm*32 + i*16 + g + half*8;
                float v0 = acc[i][j][half*2+0];
                float v1 = acc[i][j][half*2+1];
                __nv_bfloat16 h0,l0,h1,l1;
                split2(v0,h0,l0); split2(v1,h1,l1);
                size_t idx = ((size_t)b*S_ + q)*E_ + ghead*D_ + d;
                __nv_bfloat162 ph2; ph2.x=h0; ph2.y=h1;
                __nv_bfloat162 pl2; pl2.x=l0; pl2.y=l1;
                *(__nv_bfloat162*)&d_Ch[idx] = ph2;
                *(__nv_bfloat162*)&d_Cl[idx] = pl2;
            }
        }
}

// ===========================================================================
// kernel_launch
// ===========================================================================
extern "C" void kernel_launch(void* const* d_in, const int* in_sizes, int n_in,
                              void* d_out, int out_size)
{
    (void)in_sizes; (void)n_in; (void)out_size;
    const float* query = (const float*)d_in[0];
    const float* key_  = (const float*)d_in[1];
    const float* value = (const float*)d_in[2];
    const float* Wq = (const float*)d_in[3];
    const float* bq = (const float*)d_in[4];
    const float* Wk = (const float*)d_in[5];
    const float* bk = (const float*)d_in[6];
    const float* Wv = (const float*)d_in[7];
    const float* bv = (const float*)d_in[8];
    const float* hm = (const float*)d_in[9];
    const float* Wo = (const float*)d_in[10];
    const float* bo = (const float*)d_in[11];
    float* out = (float*)d_out;

    cudaFuncSetAttribute(gemm_qkv,   cudaFuncAttributeMaxDynamicSharedMemorySize, PROJ_SMEM);
    cudaFuncSetAttribute(gemm_out,   cudaFuncAttributeMaxDynamicSharedMemorySize, PROJ_SMEM);
    cudaFuncSetAttribute(scores_mma, cudaFuncAttributeMaxDynamicSharedMemorySize, SC_SMEM);
    cudaFuncSetAttribute(ctx_mma,    cudaFuncAttributeMaxDynamicSharedMemorySize, CTX_SMEM);

    const int n4 = TOK_*E_/4;

    mix_softmax_kernel<<<1, 16>>>(hm);
    split_wt3<<<dim3(32, 32, 3), dim3(32, 8)>>>(Wq, Wk, Wv);
    split_f3<<<dim3(n4/256, 1, 3), 256>>>(query, key_, value, n4);
    gemm_qkv<<<dim3(E_/128, TOK_/128, 3), 256, PROJ_SMEM>>>(bq, bk, bv);

    scores_mma<<<dim3(S_/128, S_/128, BH_), 256, SC_SMEM>>>();   // (16,16,32)
    softmax_mix_kernel<<<B_*S_, 256>>>();                        // 4096 blocks, no dyn smem
    ctx_mma<<<dim3(S_/128, BH_), 256, CTX_SMEM>>>();             // (16,32)

    split_wt<<<dim3(32, 32), dim3(32, 8)>>>(Wo);
    gemm_out<<<dim3(E_/128, TOK_/128), 256, PROJ_SMEM>>>(bo, out);
}

// round 15
// speedup vs baseline: 2.9947x; 2.9947x over previous
#include <cuda_runtime.h>
#include <cuda_bf16.h>
#include <cuda_fp16.h>
#include <cstdint>

#define B_   2
#define S_   2048
#define E_   1024
#define H_   16
#define D_   64
#define BH_  (B_*H_)      // 32
#define TOK_ (B_*S_)      // 4096

// single dynamic-smem symbol shared by all kernels
extern __shared__ __align__(16) char dynsm[];

// ===========================================================================
// helpers
// ===========================================================================
__device__ __forceinline__ uint32_t smem_u32(const void* p) {
    uint32_t a;
    asm("{ .reg .u64 t; cvta.to.shared.u64 t, %1; cvt.u32.u64 %0, t; }" : "=r"(a) : "l"(p));
    return a;
}
#define CP_COMMIT()  asm volatile("cp.async.commit_group;" ::: "memory")
#define CP_WAIT0()   asm volatile("cp.async.wait_group 0;" ::: "memory")
#define CP_WAIT1()   asm volatile("cp.async.wait_group 1;" ::: "memory")

__device__ __forceinline__ void cp16(uint32_t dst, const void* src) {
    asm volatile("cp.async.cg.shared.global [%0], [%1], 16;" :: "r"(dst), "l"(src) : "memory");
}

// m16n8k16 bf16 MMA, fp32 accum. A row-major, B col-major ([n][k] row-major).
__device__ __forceinline__ void mma_bf16(float c[4], const uint32_t a[4], const uint32_t b[2]) {
    asm volatile("mma.sync.aligned.m16n8k16.row.col.f32.bf16.bf16.f32 "
        "{%0,%1,%2,%3}, {%4,%5,%6,%7}, {%8,%9}, {%0,%1,%2,%3};"
        : "+f"(c[0]), "+f"(c[1]), "+f"(c[2]), "+f"(c[3])
        : "r"(a[0]), "r"(a[1]), "r"(a[2]), "r"(a[3]), "r"(b[0]), "r"(b[1]));
}
// m16n8k16 fp16 MMA, fp32 accum.
__device__ __forceinline__ void mma_f16(float c[4], const uint32_t a[4], const uint32_t b[2]) {
    asm volatile("mma.sync.aligned.m16n8k16.row.col.f32.f16.f16.f32 "
        "{%0,%1,%2,%3}, {%4,%5,%6,%7}, {%8,%9}, {%0,%1,%2,%3};"
        : "+f"(c[0]), "+f"(c[1]), "+f"(c[2]), "+f"(c[3])
        : "r"(a[0]), "r"(a[1]), "r"(a[2]), "r"(a[3]), "r"(b[0]), "r"(b[1]));
}

__device__ __forceinline__ void split2(float v, __nv_bfloat16& h, __nv_bfloat16& l) {
    h = __float2bfloat16(v);
    l = __float2bfloat16(v - __bfloat162float(h));
}

// A-fragment from a row-major smem tile (stride bytes), rows r0/r0+8, k-bytes kb
__device__ __forceinline__ void lda4(uint32_t a[4], const char* t, int stride, int r0, int kb) {
    a[0] = *(const uint32_t*)(t + (size_t)(r0    )*stride + kb);
    a[1] = *(const uint32_t*)(t + (size_t)(r0 + 8)*stride + kb);
    a[2] = *(const uint32_t*)(t + (size_t)(r0    )*stride + kb + 16);
    a[3] = *(const uint32_t*)(t + (size_t)(r0 + 8)*stride + kb + 16);
}
// B-fragment from [n][k] row-major tile
__device__ __forceinline__ void ldb2(uint32_t b[2], const char* t, int stride, int n, int kb) {
    b[0] = *(const uint32_t*)(t + (size_t)n*stride + kb);
    b[1] = *(const uint32_t*)(t + (size_t)n*stride + kb + 16);
}

// load [rows x 32] 16-bit-elem chunk -> smem rows of 80 bytes (64 B + 16 pad)
__device__ __forceinline__ void ld_chunk32(char* s, const void* g, int ld, int rows) {
    uint32_t sb = smem_u32(s);
    const char* gb = (const char*)g;
    for (int i = threadIdx.x; i < rows*4; i += 256) {
        int r = i >> 2, c = i & 3;
        cp16(sb + r*80 + c*16, gb + (size_t)r*ld*2 + c*16);
    }
}
// load [rows x 64] 16-bit-elem chunk -> smem rows of 144 bytes (128 B + 16 pad)
__device__ __forceinline__ void ld_chunk64(char* s, const void* g, int ld, int rows) {
    uint32_t sb = smem_u32(s);
    const char* gb = (const char*)g;
    for (int i = threadIdx.x; i < rows*8; i += 256) {
        int r = i >> 3, c = i & 7;
        cp16(sb + r*144 + c*16, gb + (size_t)r*ld*2 + c*16);
    }
}

// ===========================================================================
// static device scratch
// ===========================================================================
__device__ __half         d_Es[BH_*(size_t)S_*S_];        // 268 MB fp16 exp(s-4)
__device__ __half         d_Pf[BH_*(size_t)S_*S_];        // 268 MB fp16 P
__device__ __nv_bfloat16  d_X3h[3*TOK_*E_], d_X3l[3*TOK_*E_];  // q/k/v inputs split
__device__ __nv_bfloat16  d_W3h[3*E_*E_],  d_W3l[3*E_*E_];     // Wq/Wk/Wv^T split
__device__ __nv_bfloat16  d_Wth[E_*E_],  d_Wtl[E_*E_];         // Wo^T split
__device__ __half         d_Qf[BH_*S_*D_];                     // fp16 Q
__device__ __half         d_Kf[BH_*S_*D_];                     // fp16 K
__device__ __half         d_Vf[BH_*S_*D_];                     // fp16 V
__device__ __nv_bfloat16  d_Ch[TOK_*E_],  d_Cl[TOK_*E_];       // ctx split [B,S,E]
__device__ float          d_mixsm[H_*H_];
__device__ int            d_uniform;      // 1 if all mix rows identical (g-independent)

// ===========================================================================
// 0) softmax of the 16x16 head-mixing matrix + uniformity detection.
//    If every softmaxed row is bitwise equal to row 0, the mixed probability
//    planes are g-independent and downstream kernels collapse to one plane.
// ===========================================================================
__global__ void mix_softmax_kernel(const float* __restrict__ hm) {
    int g = threadIdx.x;
    if (g < H_) {
        float m = -1e30f;
        #pragma unroll
        for (int h = 0; h < H_; h++) m = fmaxf(m, hm[g*H_ + h]);
        float e[H_]; float s = 0.f;
        #pragma unroll
        for (int h = 0; h < H_; h++) { e[h] = expf(hm[g*H_ + h] - m); s += e[h]; }
        float inv = 1.f / s;
        #pragma unroll
        for (int h = 0; h < H_; h++) d_mixsm[g*H_ + h] = e[h] * inv;
    }
    __syncthreads();
    if (g == 0) {
        int uni = 1;
        for (int r = 1; r < H_ && uni; r++)
            for (int h = 0; h < H_; h++)
                if (__float_as_uint(d_mixsm[r*H_ + h]) != __float_as_uint(d_mixsm[h])) { uni = 0; break; }
        d_uniform = uni;
    }
}

// ===========================================================================
// 1) fp32 -> split-bf16, 3 tensors in one launch (z selects)
// ===========================================================================
__global__ __launch_bounds__(256) void split_f3(const float* __restrict__ q,
        const float* __restrict__ k, const float* __restrict__ v, int n4) {
    int z = blockIdx.z;
    const float* in = (z == 0) ? q : (z == 1) ? k : v;
    __nv_bfloat16* oh = d_X3h + (size_t)z*TOK_*E_;
    __nv_bfloat16* ol = d_X3l + (size_t)z*TOK_*E_;
    int i = blockIdx.x*256 + threadIdx.x;
    if (i >= n4) return;
    float4 vv = ((const float4*)in)[i];
    __nv_bfloat16 h0,h1,h2,h3,l0,l1,l2,l3;
    split2(vv.x,h0,l0); split2(vv.y,h1,l1); split2(vv.z,h2,l2); split2(vv.w,h3,l3);
    __nv_bfloat162 p;
    p.x=h0; p.y=h1; ((__nv_bfloat162*)oh)[2*i]   = p;
    p.x=h2; p.y=h3; ((__nv_bfloat162*)oh)[2*i+1] = p;
    p.x=l0; p.y=l1; ((__nv_bfloat162*)ol)[2*i]   = p;
    p.x=l2; p.y=l3; ((__nv_bfloat162*)ol)[2*i+1] = p;
}

// ===========================================================================
// 2) W [K,N] fp32 -> W^T [N,K] split-bf16. wt3: 3 weights in one launch.
// ===========================================================================
__device__ __forceinline__ void wt_body(const float* __restrict__ W,
        __nv_bfloat16* __restrict__ oh, __nv_bfloat16* __restrict__ ol) {
    __shared__ float t[32][33];
    int n0 = blockIdx.x*32, k0 = blockIdx.y*32;
    int tx = threadIdx.x, ty = threadIdx.y;
    #pragma unroll
    for (int i = 0; i < 4; i++)
        t[ty+8*i][tx] = W[(size_t)(k0+ty+8*i)*E_ + n0+tx];
    __syncthreads();
    #pragma unroll
    for (int i = 0; i < 4; i++) {
        float v = t[tx][ty+8*i];
        size_t idx = (size_t)(n0+ty+8*i)*E_ + k0 + tx;
        __nv_bfloat16 hb, lb; split2(v, hb, lb);
        oh[idx] = hb; ol[idx] = lb;
    }
}
__global__ void split_wt3(const float* __restrict__ Wq,
        const float* __restrict__ Wk, const float* __restrict__ Wv) {
    int z = blockIdx.z;
    const float* W = (z == 0) ? Wq : (z == 1) ? Wk : Wv;
    wt_body(W, d_W3h + (size_t)z*E_*E_, d_W3l + (size_t)z*E_*E_);
}
__global__ void split_wt(const float* __restrict__ W) {
    wt_body(W, d_Wth, d_Wtl);
}

// ===========================================================================
// 3a) QKV projection GEMM, z in {0,1,2}. 128x128 block, 8 warps @ 32x64.
//     Computed split-bf16 (3-product, accurate); epilogue stores fp16
//     [B,H,S,D] for all of Q, K, V.
// ===========================================================================
#define PROJ_SMEM (2*4*10240)   // 81920
__global__ __launch_bounds__(256) void gemm_qkv(
    const float* __restrict__ bq, const float* __restrict__ bk,
    const float* __restrict__ bv)
{
    char* sm = dynsm;
    const int z = blockIdx.z;
    const float* bias = (z == 0) ? bq : (z == 1) ? bk : bv;
    __half* outP = (z == 0) ? d_Qf : (z == 1) ? d_Kf : d_Vf;
    const __nv_bfloat16* Ah_ = d_X3h + (size_t)z*TOK_*E_;
    const __nv_bfloat16* Al_ = d_X3l + (size_t)z*TOK_*E_;
    const __nv_bfloat16* Bh_ = d_W3h + (size_t)z*E_*E_;
    const __nv_bfloat16* Bl_ = d_W3l + (size_t)z*E_*E_;

    const int tid = threadIdx.x, lane = tid & 31, wid = tid >> 5;
    const int wm = wid >> 1, wn = wid & 1;
    const int g = lane >> 2, tg = lane & 3;
    const int bm = blockIdx.y*128, bn = blockIdx.x*128;

    float acc[2][8][4];
    #pragma unroll
    for (int i = 0; i < 2; i++)
        #pragma unroll
        for (int j = 0; j < 8; j++)
            #pragma unroll
            for (int q = 0; q < 4; q++) acc[i][j][q] = 0.f;

    const __nv_bfloat16* gT[4] = { Ah_ + (size_t)bm*E_, Al_ + (size_t)bm*E_,
                                   Bh_ + (size_t)bn*E_, Bl_ + (size_t)bn*E_ };
    #pragma unroll
    for (int t = 0; t < 4; t++) ld_chunk32(sm + t*10240, gT[t], E_, 128);
    CP_COMMIT();

    for (int c = 0; c < 32; c++) {
        if (c < 31) {
            int k0 = (c+1)*32;
            char* st = sm + ((c+1)&1)*40960;
            #pragma unroll
            for (int t = 0; t < 4; t++) ld_chunk32(st + t*10240, gT[t] + k0, E_, 128);
            CP_COMMIT(); CP_WAIT1();
        } else CP_WAIT0();
        __syncthreads();
        const char* st = sm + (c&1)*40960;
        #pragma unroll
        for (int ks = 0; ks < 2; ks++) {
            int kb = ks*32 + tg*4;
            uint32_t aH[2][4], aL[2][4], bH[8][2], bL[8][2];
            #pragma unroll
            for (int i = 0; i < 2; i++) {
                int r0 = wm*32 + i*16 + g;
                lda4(aH[i], st,          80, r0, kb);
                lda4(aL[i], st + 10240,  80, r0, kb);
            }
            #pragma unroll
            for (int j = 0; j < 8; j++) {
                int n = wn*64 + j*8 + g;
                ldb2(bH[j], st + 20480, 80, n, kb);
                ldb2(bL[j], st + 30720, 80, n, kb);
            }
            #pragma unroll
            for (int i = 0; i < 2; i++)
                #pragma unroll
                for (int j = 0; j < 8; j++) {
                    mma_bf16(acc[i][j], aH[i], bH[j]);
                    mma_bf16(acc[i][j], aH[i], bL[j]);
                    mma_bf16(acc[i][j], aL[i], bH[j]);
                }
        }
        __syncthreads();
    }

    #pragma unroll
    for (int j = 0; j < 8; j++) {
        int c = bn + wn*64 + j*8 + tg*2;
        float b0 = bias[c], b1 = bias[c+1];
        #pragma unroll
        for (int i = 0; i < 2; i++) {
            #pragma unroll
            for (int half = 0; half < 2; half++) {
                int r = bm + wm*32 + i*16 + g + half*8;
                float v0 = acc[i][j][half*2+0] + b0;
                float v1 = acc[i][j][half*2+1] + b1;
                int bb = r >> 11, s = r & (S_-1);
                int h = c >> 6,  d = c & 63;
                size_t idx = (((size_t)bb*H_ + h)*S_ + s)*D_ + d;
                *(__half2*)&outP[idx] = __floats2half2_rn(v0, v1);
            }
        }
    }
}

// ===========================================================================
// 3b) output projection GEMM: out[4096,1024] fp32 = C @ Wo^T + bo
// ===========================================================================
__global__ __launch_bounds__(256) void gemm_out(
    const float* __restrict__ bias, float* __restrict__ outF)
{
    char* sm = dynsm;
    const int tid = threadIdx.x, lane = tid & 31, wid = tid >> 5;
    const int wm = wid >> 1, wn = wid & 1;
    const int g = lane >> 2, tg = lane & 3;
    const int bm = blockIdx.y*128, bn = blockIdx.x*128;

    float acc[2][8][4];
    #pragma unroll
    for (int i = 0; i < 2; i++)
        #pragma unroll
        for (int j = 0; j < 8; j++)
            #pragma unroll
            for (int q = 0; q < 4; q++) acc[i][j][q] = 0.f;

    const __nv_bfloat16* gT[4] = { d_Ch + (size_t)bm*E_, d_Cl + (size_t)bm*E_,
                                   d_Wth + (size_t)bn*E_, d_Wtl + (size_t)bn*E_ };
    #pragma unroll
    for (int t = 0; t < 4; t++) ld_chunk32(sm + t*10240, gT[t], E_, 128);
    CP_COMMIT();

    for (int c = 0; c < 32; c++) {
        if (c < 31) {
            int k0 = (c+1)*32;
            char* st = sm + ((c+1)&1)*40960;
            #pragma unroll
            for (int t = 0; t < 4; t++) ld_chunk32(st + t*10240, gT[t] + k0, E_, 128);
            CP_COMMIT(); CP_WAIT1();
        } else CP_WAIT0();
        __syncthreads();
        const char* st = sm + (c&1)*40960;
        #pragma unroll
        for (int ks = 0; ks < 2; ks++) {
            int kb = ks*32 + tg*4;
            uint32_t aH[2][4], aL[2][4], bH[8][2], bL[8][2];
            #pragma unroll
            for (int i = 0; i < 2; i++) {
                int r0 = wm*32 + i*16 + g;
                lda4(aH[i], st,          80, r0, kb);
                lda4(aL[i], st + 10240,  80, r0, kb);
            }
            #pragma unroll
            for (int j = 0; j < 8; j++) {
                int n = wn*64 + j*8 + g;
                ldb2(bH[j], st + 20480, 80, n, kb);
                ldb2(bL[j], st + 30720, 80, n, kb);
            }
            #pragma unroll
            for (int i = 0; i < 2; i++)
                #pragma unroll
                for (int j = 0; j < 8; j++) {
                    mma_bf16(acc[i][j], aH[i], bH[j]);
                    mma_bf16(acc[i][j], aH[i], bL[j]);
                    mma_bf16(acc[i][j], aL[i], bH[j]);
                }
        }
        __syncthreads();
    }

    #pragma unroll
    for (int j = 0; j < 8; j++) {
        int c = bn + wn*64 + j*8 + tg*2;
        float b0 = bias[c], b1 = bias[c+1];
        #pragma unroll
        for (int i = 0; i < 2; i++) {
            #pragma unroll
            for (int half = 0; half < 2; half++) {
                int r = bm + wm*32 + i*16 + g + half*8;
                float2 f;
                f.x = acc[i][j][half*2+0] + b0;
                f.y = acc[i][j][half*2+1] + b1;
                *(float2*)&outF[(size_t)r*E_ + c] = f;
            }
        }
    }
}

// ===========================================================================
// 4) exp-scores: E = exp(Q K^T / 8 - 4) per (b,h), stored fp16.
//    Single fp16 product (Q,K stored fp16; products exact in fp32 accum).
//    128x128 block, K=64 single-shot.  (round-13 version, no psums)
// ===========================================================================
#define SC_SMEM (2*18432)   // 36864
__global__ __launch_bounds__(256) void scores_mma()
{
    char* sm = dynsm;
    const int tid = threadIdx.x, lane = tid & 31, wid = tid >> 5;
    const int wm = wid >> 1, wn = wid & 1;
    const int g = lane >> 2, tg = lane & 3;
    const int bh = blockIdx.z;
    const int bm = blockIdx.y*128, bn = blockIdx.x*128;

    ld_chunk64(sm,           d_Qf + (size_t)bh*S_*D_ + (size_t)bm*D_, D_, 128);
    ld_chunk64(sm + 18432,   d_Kf + (size_t)bh*S_*D_ + (size_t)bn*D_, D_, 128);
    CP_COMMIT(); CP_WAIT0();
    __syncthreads();

    float acc[2][8][4];
    #pragma unroll
    for (int i = 0; i < 2; i++)
        #pragma unroll
        for (int j = 0; j < 8; j++)
            #pragma unroll
            for (int q = 0; q < 4; q++) acc[i][j][q] = 0.f;

    #pragma unroll
    for (int ks = 0; ks < 4; ks++) {
        int kb = ks*32 + tg*4;
        uint32_t aF[2][4], bF[8][2];
        #pragma unroll
        for (int i = 0; i < 2; i++) {
            int r0 = wm*32 + i*16 + g;
            lda4(aF[i], sm, 144, r0, kb);
        }
        #pragma unroll
        for (int j = 0; j < 8; j++) {
            int n = wn*64 + j*8 + g;
            ldb2(bF[j], sm + 18432, 144, n, kb);
        }
        #pragma unroll
        for (int i = 0; i < 2; i++)
            #pragma unroll
            for (int j = 0; j < 8; j++)
                mma_f16(acc[i][j], aF[i], bF[j]);
    }

    __half* outb = d_Es + (size_t)bh*S_*S_;
    #pragma unroll
    for (int i = 0; i < 2; i++)
        #pragma unroll
        for (int j = 0; j < 8; j++) {
            int c = bn + wn*64 + j*8 + tg*2;
            #pragma unroll
            for (int half = 0; half < 2; half++) {
                int r = bm + wm*32 + i*16 + g + half*8;
                float e0 = __expf(acc[i][j][half*2+0] * 0.125f - 4.f);
                float e1 = __expf(acc[i][j][half*2+1] * 0.125f - 4.f);
                *(__half2*)&outb[(size_t)r*S_ + c] = __floats2half2_rn(e0, e1);
            }
        }
}

// ===========================================================================
// 5) fused normalize + head mixing (round-13 smem-staged structure).
//    Block per (b,q). If mix rows are uniform (d_uniform), all mixed planes
//    are identical: compute/store plane 0 only (16x less mixing work).
// ===========================================================================
#define SMX_SMEM ((H_*S_ + 16 + 256)*4)   // 132160
__global__ __launch_bounds__(256) void softmax_mix_kernel()
{
    float* sm   = (float*)dynsm;
    float* inv  = sm + H_*S_;
    float* mixs = inv + 16;
    const int bq = blockIdx.x;
    const int b = bq >> 11, q = bq & (S_-1);
    const int tid = threadIdx.x;
    const int uni = d_uniform;

    const __half* src = d_Es + ((size_t)b*H_)*S_*S_ + (size_t)q*S_;
    for (int i = tid; i < H_*S_/8; i += 256) {
        int h = i >> 8, k8 = i & 255;          // S_/8 = 256 chunks per head
        const __half2* p = (const __half2*)(src + (size_t)h*S_*S_ + k8*8);
        float* dst = sm + h*S_ + k8*8;
        #pragma unroll
        for (int u = 0; u < 4; u++) {
            float2 f = __half22float2(p[u]);
            dst[u*2+0] = f.x; dst[u*2+1] = f.y;
        }
    }
    mixs[tid] = d_mixsm[tid & 255];
    __syncthreads();

    int w = tid >> 5, lane = tid & 31;
    #pragma unroll
    for (int hh = 0; hh < 2; hh++) {
        int h = w*2 + hh;
        float* row = sm + h*S_;
        float s = 0.f;
        for (int j = lane; j < S_; j += 32) s += row[j];
        #pragma unroll
        for (int o = 16; o; o >>= 1) s += __shfl_xor_sync(0xFFFFFFFFu, s, o);
        if (lane == 0) inv[h] = 1.f / s;
    }
    __syncthreads();

    size_t obase = ((size_t)b*H_)*S_*S_ + (size_t)q*S_;
    if (uni) {
        // all mixed planes identical -> plane 0 only
        for (int k2 = tid; k2 < S_/2; k2 += 256) {
            int k0 = k2*2;
            float o0 = 0.f, o1 = 0.f;
            #pragma unroll
            for (int h = 0; h < H_; h++) {
                float mh = mixs[h];
                o0 = fmaf(mh, sm[h*S_ + k0]     * inv[h], o0);
                o1 = fmaf(mh, sm[h*S_ + k0 + 1] * inv[h], o1);
            }
            *(__half2*)&d_Pf[obase + k0] = __floats2half2_rn(o0, o1);
        }
    } else {
        for (int k2 = tid; k2 < S_/2; k2 += 256) {
            int k0 = k2*2;
            float a0[H_], a1[H_];
            #pragma unroll
            for (int h = 0; h < H_; h++) {
                a0[h] = sm[h*S_ + k0]     * inv[h];
                a1[h] = sm[h*S_ + k0 + 1] * inv[h];
            }
            #pragma unroll
            for (int g = 0; g < H_; g++) {
                float o0 = 0.f, o1 = 0.f;
                #pragma unroll
                for (int h = 0; h < H_; h++) {
                    o0 = fmaf(mixs[g*16 + h], a0[h], o0);
                    o1 = fmaf(mixs[g*16 + h], a1[h], o1);
                }
                size_t idx = obase + (size_t)g*S_*S_ + k0;
                *(__half2*)&d_Pf[idx] = __floats2half2_rn(o0, o1);
            }
        }
    }
}

// ===========================================================================
// 6) ctx = P @ V per (b,g), fp16 single-product. 128x64 block, 8 warps.
//    If d_uniform, all P planes equal -> read plane 0 (L2-resident reuse).
// ===========================================================================
#define CTX_STAGE (10240 + 4608)          // 14848
#define CTX_SMEM  (2*CTX_STAGE)           // 29696
__global__ __launch_bounds__(256) void ctx_mma()
{
    char* sm = dynsm;
    const int tid = threadIdx.x, lane = tid & 31, wid = tid >> 5;
    const int wm = wid >> 1, wn = wid & 1;
    const int g = lane >> 2, tg = lane & 3;
    const int bg = blockIdx.y;
    const int b = bg >> 4, ghead = bg & 15;
    const int bm = blockIdx.x*128;
    const int psel = d_uniform ? (b*H_) : bg;

    const __half* pf = d_Pf + (size_t)psel*S_*S_ + (size_t)bm*S_;
    const __half* vf = d_Vf + (size_t)bg*S_*D_;

    float acc[2][4][4];
    #pragma unroll
    for (int i = 0; i < 2; i++)
        #pragma unroll
        for (int j = 0; j < 4; j++)
            #pragma unroll
            for (int q = 0; q < 4; q++) acc[i][j][q] = 0.f;

    {   // preload chunk 0
        char* st = sm;
        ld_chunk32(st,         pf, S_, 128);
        ld_chunk64(st + 10240, vf, D_, 32);
        CP_COMMIT();
    }
    for (int c = 0; c < 64; c++) {
        if (c < 63) {
            int k0 = (c+1)*32;
            char* st = sm + ((c+1)&1)*CTX_STAGE;
            ld_chunk32(st,         pf + k0, S_, 128);
            ld_chunk64(st + 10240, vf + (size_t)k0*D_, D_, 32);
            CP_COMMIT(); CP_WAIT1();
        } else CP_WAIT0();
        __syncthreads();
        const char* st = sm + (c&1)*CTX_STAGE;
        const char* vF = st + 10240;
        #pragma unroll
        for (int ks = 0; ks < 2; ks++) {
            int kb = ks*32 + tg*4;
            uint32_t aF[2][4], bF[4][2];
            #pragma unroll
            for (int i = 0; i < 2; i++) {
                int r0 = wm*32 + i*16 + g;
                lda4(aF[i], st, 80, r0, kb);
            }
            int krow = ks*16 + tg*2;
            #pragma unroll
            for (int j = 0; j < 4; j++) {
                int n2 = (wn*32 + j*8 + g)*2;
                uint32_t x0, x1, x2, x3;
                x0 = *(const unsigned short*)(vF + (krow  )*144 + n2);
                x1 = *(const unsigned short*)(vF + (krow+1)*144 + n2);
                x2 = *(const unsigned short*)(vF + (krow+8)*144 + n2);
                x3 = *(const unsigned short*)(vF + (krow+9)*144 + n2);
                bF[j][0] = x0 | (x1 << 16);
                bF[j][1] = x2 | (x3 << 16);
            }
            #pragma unroll
            for (int i = 0; i < 2; i++)
                #pragma unroll
                for (int j = 0; j < 4; j++)
                    mma_f16(acc[i][j], aF[i], bF[j]);
        }
        __syncthreads();
    }

    #pragma unroll
    for (int i = 0; i < 2; i++)
        #pragma unroll
        for (int j = 0; j < 4; j++) {
            int d = wn*32 + j*8 + tg*2;
            #pragma unroll
            for (int half = 0; half < 2; half++) {
                int q = bm + wm*32 + i*16 + g + half*8;
                float v0 = acc[i][j][half*2+0];
                float v1 = acc[i][j][half*2+1];
                __nv_bfloat16 h0,l0,h1,l1;
                split2(v0,h0,l0); split2(v1,h1,l1);
                size_t idx = ((size_t)b*S_ + q)*E_ + ghead*D_ + d;
                __nv_bfloat162 ph2; ph2.x=h0; ph2.y=h1;
                __nv_bfloat162 pl2; pl2.x=l0; pl2.y=l1;
                *(__nv_bfloat162*)&d_Ch[idx] = ph2;
                *(__nv_bfloat162*)&d_Cl[idx] = pl2;
            }
        }
}

// ===========================================================================
// kernel_launch
// ===========================================================================
extern "C" void kernel_launch(void* const* d_in, const int* in_sizes, int n_in,
                              void* d_out, int out_size)
{
    (void)in_sizes; (void)n_in; (void)out_size;
    const float* query = (const float*)d_in[0];
    const float* key_  = (const float*)d_in[1];
    const float* value = (const float*)d_in[2];
    const float* Wq = (const float*)d_in[3];
    const float* bq = (const float*)d_in[4];
    const float* Wk = (const float*)d_in[5];
    const float* bk = (const float*)d_in[6];
    const float* Wv = (const float*)d_in[7];
    const float* bv = (const float*)d_in[8];
    const float* hm = (const float*)d_in[9];
    const float* Wo = (const float*)d_in[10];
    const float* bo = (const float*)d_in[11];
    float* out = (float*)d_out;

    cudaFuncSetAttribute(gemm_qkv,           cudaFuncAttributeMaxDynamicSharedMemorySize, PROJ_SMEM);
    cudaFuncSetAttribute(gemm_out,           cudaFuncAttributeMaxDynamicSharedMemorySize, PROJ_SMEM);
    cudaFuncSetAttribute(scores_mma,         cudaFuncAttributeMaxDynamicSharedMemorySize, SC_SMEM);
    cudaFuncSetAttribute(softmax_mix_kernel, cudaFuncAttributeMaxDynamicSharedMemorySize, SMX_SMEM);
    cudaFuncSetAttribute(ctx_mma,            cudaFuncAttributeMaxDynamicSharedMemorySize, CTX_SMEM);

    const int n4 = TOK_*E_/4;

    mix_softmax_kernel<<<1, 16>>>(hm);
    split_wt3<<<dim3(32, 32, 3), dim3(32, 8)>>>(Wq, Wk, Wv);
    split_f3<<<dim3(n4/256, 1, 3), 256>>>(query, key_, value, n4);
    gemm_qkv<<<dim3(E_/128, TOK_/128, 3), 256, PROJ_SMEM>>>(bq, bk, bv);

    scores_mma<<<dim3(S_/128, S_/128, BH_), 256, SC_SMEM>>>();   // (16,16,32)
    softmax_mix_kernel<<<B_*S_, 256, SMX_SMEM>>>();              // 4096 blocks
    ctx_mma<<<dim3(S_/128, BH_), 256, CTX_SMEM>>>();             // (16,32)

    split_wt<<<dim3(32, 32), dim3(32, 8)>>>(Wo);
    gemm_out<<<dim3(E_/128, TOK_/128), 256, PROJ_SMEM>>>(bo, out);
}

// round 17
// speedup vs baseline: 3.5185x; 1.1749x over previous
#include <cuda_runtime.h>
#include <cuda_bf16.h>
#include <cuda_fp16.h>
#include <cstdint>

#define B_   2
#define S_   2048
#define E_   1024
#define H_   16
#define D_   64
#define BH_  (B_*H_)      // 32
#define TOK_ (B_*S_)      // 4096

// single dynamic-smem symbol shared by all kernels
extern __shared__ __align__(16) char dynsm[];

// ===========================================================================
// helpers
// ===========================================================================
__device__ __forceinline__ uint32_t smem_u32(const void* p) {
    uint32_t a;
    asm("{ .reg .u64 t; cvta.to.shared.u64 t, %1; cvt.u32.u64 %0, t; }" : "=r"(a) : "l"(p));
    return a;
}
#define CP_COMMIT()  asm volatile("cp.async.commit_group;" ::: "memory")
#define CP_WAIT0()   asm volatile("cp.async.wait_group 0;" ::: "memory")
#define CP_WAIT1()   asm volatile("cp.async.wait_group 1;" ::: "memory")

__device__ __forceinline__ void cp16(uint32_t dst, const void* src) {
    asm volatile("cp.async.cg.shared.global [%0], [%1], 16;" :: "r"(dst), "l"(src) : "memory");
}

// m16n8k16 bf16 MMA, fp32 accum. A row-major, B col-major ([n][k] row-major).
__device__ __forceinline__ void mma_bf16(float c[4], const uint32_t a[4], const uint32_t b[2]) {
    asm volatile("mma.sync.aligned.m16n8k16.row.col.f32.bf16.bf16.f32 "
        "{%0,%1,%2,%3}, {%4,%5,%6,%7}, {%8,%9}, {%0,%1,%2,%3};"
        : "+f"(c[0]), "+f"(c[1]), "+f"(c[2]), "+f"(c[3])
        : "r"(a[0]), "r"(a[1]), "r"(a[2]), "r"(a[3]), "r"(b[0]), "r"(b[1]));
}
// m16n8k16 fp16 MMA, fp32 accum.
__device__ __forceinline__ void mma_f16(float c[4], const uint32_t a[4], const uint32_t b[2]) {
    asm volatile("mma.sync.aligned.m16n8k16.row.col.f32.f16.f16.f32 "
        "{%0,%1,%2,%3}, {%4,%5,%6,%7}, {%8,%9}, {%0,%1,%2,%3};"
        : "+f"(c[0]), "+f"(c[1]), "+f"(c[2]), "+f"(c[3])
        : "r"(a[0]), "r"(a[1]), "r"(a[2]), "r"(a[3]), "r"(b[0]), "r"(b[1]));
}

__device__ __forceinline__ void split2(float v, __nv_bfloat16& h, __nv_bfloat16& l) {
    h = __float2bfloat16(v);
    l = __float2bfloat16(v - __bfloat162float(h));
}

// A-fragment from a row-major smem tile (stride bytes), rows r0/r0+8, k-bytes kb
__device__ __forceinline__ void lda4(uint32_t a[4], const char* t, int stride, int r0, int kb) {
    a[0] = *(const uint32_t*)(t + (size_t)(r0    )*stride + kb);
    a[1] = *(const uint32_t*)(t + (size_t)(r0 + 8)*stride + kb);
    a[2] = *(const uint32_t*)(t + (size_t)(r0    )*stride + kb + 16);
    a[3] = *(const uint32_t*)(t + (size_t)(r0 + 8)*stride + kb + 16);
}
// B-fragment from [n][k] row-major tile
__device__ __forceinline__ void ldb2(uint32_t b[2], const char* t, int stride, int n, int kb) {
    b[0] = *(const uint32_t*)(t + (size_t)n*stride + kb);
    b[1] = *(const uint32_t*)(t + (size_t)n*stride + kb + 16);
}

// load [rows x 32] 16-bit-elem chunk -> smem rows of 80 bytes (64 B + 16 pad)
__device__ __forceinline__ void ld_chunk32(char* s, const void* g, int ld, int rows) {
    uint32_t sb = smem_u32(s);
    const char* gb = (const char*)g;
    for (int i = threadIdx.x; i < rows*4; i += 256) {
        int r = i >> 2, c = i & 3;
        cp16(sb + r*80 + c*16, gb + (size_t)r*ld*2 + c*16);
    }
}
// load [rows x 64] 16-bit-elem chunk -> smem rows of 144 bytes (128 B + 16 pad)
__device__ __forceinline__ void ld_chunk64(char* s, const void* g, int ld, int rows) {
    uint32_t sb = smem_u32(s);
    const char* gb = (const char*)g;
    for (int i = threadIdx.x; i < rows*8; i += 256) {
        int r = i >> 3, c = i & 7;
        cp16(sb + r*144 + c*16, gb + (size_t)r*ld*2 + c*16);
    }
}

// ===========================================================================
// static device scratch
// ===========================================================================
__device__ __half         d_Es[BH_*(size_t)S_*S_];        // 268 MB fp16 exp(s-4)
__device__ __half         d_Pf[BH_*(size_t)S_*S_];        // 268 MB fp16 P
__device__ __half         d_X3f[3*TOK_*E_];               // q/k/v inputs fp16
__device__ __half         d_W3f[3*E_*E_];                 // Wq/Wk/Wv^T fp16
__device__ __nv_bfloat16  d_Wth[E_*E_],  d_Wtl[E_*E_];    // Wo^T split (for gemm_out)
__device__ __half         d_Qf[BH_*S_*D_];                // fp16 Q
__device__ __half         d_Kf[BH_*S_*D_];                // fp16 K
__device__ __half         d_Vf[BH_*S_*D_];                // fp16 V
__device__ __nv_bfloat16  d_Ch[TOK_*E_],  d_Cl[TOK_*E_];  // ctx split [B,S,E]
__device__ float          d_mixsm[H_*H_];
__device__ int            d_uniform;      // 1 if all mix rows identical (g-independent)

// ===========================================================================
// 0) softmax of the 16x16 head-mixing matrix + uniformity detection.
// ===========================================================================
__global__ void mix_softmax_kernel(const float* __restrict__ hm) {
    int g = threadIdx.x;
    if (g < H_) {
        float m = -1e30f;
        #pragma unroll
        for (int h = 0; h < H_; h++) m = fmaxf(m, hm[g*H_ + h]);
        float e[H_]; float s = 0.f;
        #pragma unroll
        for (int h = 0; h < H_; h++) { e[h] = expf(hm[g*H_ + h] - m); s += e[h]; }
        float inv = 1.f / s;
        #pragma unroll
        for (int h = 0; h < H_; h++) d_mixsm[g*H_ + h] = e[h] * inv;
    }
    __syncthreads();
    if (g == 0) {
        int uni = 1;
        for (int r = 1; r < H_ && uni; r++)
            for (int h = 0; h < H_; h++)
                if (__float_as_uint(d_mixsm[r*H_ + h]) != __float_as_uint(d_mixsm[h])) { uni = 0; break; }
        d_uniform = uni;
    }
}

// ===========================================================================
// 1) fp32 -> fp16, 3 tensors in one launch (z selects)
// ===========================================================================
__global__ __launch_bounds__(256) void split_f3(const float* __restrict__ q,
        const float* __restrict__ k, const float* __restrict__ v, int n4) {
    int z = blockIdx.z;
    const float* in = (z == 0) ? q : (z == 1) ? k : v;
    __half* of = d_X3f + (size_t)z*TOK_*E_;
    int i = blockIdx.x*256 + threadIdx.x;
    if (i >= n4) return;
    float4 vv = ((const float4*)in)[i];
    ((__half2*)of)[2*i]   = __floats2half2_rn(vv.x, vv.y);
    ((__half2*)of)[2*i+1] = __floats2half2_rn(vv.z, vv.w);
}

// ===========================================================================
// 2a) W [K,N] fp32 -> W^T [N,K] fp16, 3 weights in one launch.
// ===========================================================================
__global__ void split_wt3(const float* __restrict__ Wq,
        const float* __restrict__ Wk, const float* __restrict__ Wv) {
    __shared__ float t[32][33];
    int z = blockIdx.z;
    const float* W = (z == 0) ? Wq : (z == 1) ? Wk : Wv;
    __half* of = d_W3f + (size_t)z*E_*E_;
    int n0 = blockIdx.x*32, k0 = blockIdx.y*32;
    int tx = threadIdx.x, ty = threadIdx.y;
    #pragma unroll
    for (int i = 0; i < 4; i++)
        t[ty+8*i][tx] = W[(size_t)(k0+ty+8*i)*E_ + n0+tx];
    __syncthreads();
    #pragma unroll
    for (int i = 0; i < 4; i++) {
        float v = t[tx][ty+8*i];
        of[(size_t)(n0+ty+8*i)*E_ + k0 + tx] = __float2half_rn(v);
    }
}
// 2b) Wo [K,N] fp32 -> Wo^T [N,K] split-bf16 (output projection stays accurate)
__global__ void split_wt(const float* __restrict__ W) {
    __shared__ float t[32][33];
    int n0 = blockIdx.x*32, k0 = blockIdx.y*32;
    int tx = threadIdx.x, ty = threadIdx.y;
    #pragma unroll
    for (int i = 0; i < 4; i++)
        t[ty+8*i][tx] = W[(size_t)(k0+ty+8*i)*E_ + n0+tx];
    __syncthreads();
    #pragma unroll
    for (int i = 0; i < 4; i++) {
        float v = t[tx][ty+8*i];
        size_t idx = (size_t)(n0+ty+8*i)*E_ + k0 + tx;
        __nv_bfloat16 hb, lb; split2(v, hb, lb);
        d_Wth[idx] = hb; d_Wtl[idx] = lb;
    }
}

// ===========================================================================
// 3a) QKV projection GEMM, z in {0,1,2}. 128x128 block, 8 warps @ 32x64.
//     Single-product fp16 (X fp16, W^T fp16); epilogue stores fp16 [B,H,S,D].
// ===========================================================================
#define PROJ_SMEM (2*2*10240)   // 40960
__global__ __launch_bounds__(256) void gemm_qkv(
    const float* __restrict__ bq, const float* __restrict__ bk,
    const float* __restrict__ bv)
{
    char* sm = dynsm;
    const int z = blockIdx.z;
    const float* bias = (z == 0) ? bq : (z == 1) ? bk : bv;
    __half* outP = (z == 0) ? d_Qf : (z == 1) ? d_Kf : d_Vf;
    const __half* Ax = d_X3f + (size_t)z*TOK_*E_;
    const __half* Bw = d_W3f + (size_t)z*E_*E_;

    const int tid = threadIdx.x, lane = tid & 31, wid = tid >> 5;
    const int wm = wid >> 1, wn = wid & 1;
    const int g = lane >> 2, tg = lane & 3;
    const int bm = blockIdx.y*128, bn = blockIdx.x*128;

    float acc[2][8][4];
    #pragma unroll
    for (int i = 0; i < 2; i++)
        #pragma unroll
        for (int j = 0; j < 8; j++)
            #pragma unroll
            for (int q = 0; q < 4; q++) acc[i][j][q] = 0.f;

    const __half* gA = Ax + (size_t)bm*E_;
    const __half* gB = Bw + (size_t)bn*E_;
    ld_chunk32(sm,         gA, E_, 128);
    ld_chunk32(sm + 10240, gB, E_, 128);
    CP_COMMIT();

    for (int c = 0; c < 32; c++) {
        if (c < 31) {
            int k0 = (c+1)*32;
            char* st = sm + ((c+1)&1)*20480;
            ld_chunk32(st,         gA + k0, E_, 128);
            ld_chunk32(st + 10240, gB + k0, E_, 128);
            CP_COMMIT(); CP_WAIT1();
        } else CP_WAIT0();
        __syncthreads();
        const char* st = sm + (c&1)*20480;
        #pragma unroll
        for (int ks = 0; ks < 2; ks++) {
            int kb = ks*32 + tg*4;
            uint32_t aF[2][4], bF[8][2];
            #pragma unroll
            for (int i = 0; i < 2; i++) {
                int r0 = wm*32 + i*16 + g;
                lda4(aF[i], st, 80, r0, kb);
            }
            #pragma unroll
            for (int j = 0; j < 8; j++) {
                int n = wn*64 + j*8 + g;
                ldb2(bF[j], st + 10240, 80, n, kb);
            }
            #pragma unroll
            for (int i = 0; i < 2; i++)
                #pragma unroll
                for (int j = 0; j < 8; j++)
                    mma_f16(acc[i][j], aF[i], bF[j]);
        }
        __syncthreads();
    }

    #pragma unroll
    for (int j = 0; j < 8; j++) {
        int c = bn + wn*64 + j*8 + tg*2;
        float b0 = bias[c], b1 = bias[c+1];
        #pragma unroll
        for (int i = 0; i < 2; i++) {
            #pragma unroll
            for (int half = 0; half < 2; half++) {
                int r = bm + wm*32 + i*16 + g + half*8;
                float v0 = acc[i][j][half*2+0] + b0;
                float v1 = acc[i][j][half*2+1] + b1;
                int bb = r >> 11, s = r & (S_-1);
                int h = c >> 6,  d = c & 63;
                size_t idx = (((size_t)bb*H_ + h)*S_ + s)*D_ + d;
                *(__half2*)&outP[idx] = __floats2half2_rn(v0, v1);
            }
        }
    }
}

// ===========================================================================
// 3b) output projection GEMM: out[4096,1024] fp32 = C @ Wo^T + bo
//     (split-bf16 3-product; the most error-sensitive GEMM)
// ===========================================================================
#define OUT_SMEM (2*4*10240)   // 81920
__global__ __launch_bounds__(256) void gemm_out(
    const float* __restrict__ bias, float* __restrict__ outF)
{
    char* sm = dynsm;
    const int tid = threadIdx.x, lane = tid & 31, wid = tid >> 5;
    const int wm = wid >> 1, wn = wid & 1;
    const int g = lane >> 2, tg = lane & 3;
    const int bm = blockIdx.y*128, bn = blockIdx.x*128;

    float acc[2][8][4];
    #pragma unroll
    for (int i = 0; i < 2; i++)
        #pragma unroll
        for (int j = 0; j < 8; j++)
            #pragma unroll
            for (int q = 0; q < 4; q++) acc[i][j][q] = 0.f;

    const __nv_bfloat16* gT[4] = { d_Ch + (size_t)bm*E_, d_Cl + (size_t)bm*E_,
                                   d_Wth + (size_t)bn*E_, d_Wtl + (size_t)bn*E_ };
    #pragma unroll
    for (int t = 0; t < 4; t++) ld_chunk32(sm + t*10240, gT[t], E_, 128);
    CP_COMMIT();

    for (int c = 0; c < 32; c++) {
        if (c < 31) {
            int k0 = (c+1)*32;
            char* st = sm + ((c+1)&1)*40960;
            #pragma unroll
            for (int t = 0; t < 4; t++) ld_chunk32(st + t*10240, gT[t] + k0, E_, 128);
            CP_COMMIT(); CP_WAIT1();
        } else CP_WAIT0();
        __syncthreads();
        const char* st = sm + (c&1)*40960;
        #pragma unroll
        for (int ks = 0; ks < 2; ks++) {
            int kb = ks*32 + tg*4;
            uint32_t aH[2][4], aL[2][4], bH[8][2], bL[8][2];
            #pragma unroll
            for (int i = 0; i < 2; i++) {
                int r0 = wm*32 + i*16 + g;
                lda4(aH[i], st,          80, r0, kb);
                lda4(aL[i], st + 10240,  80, r0, kb);
            }
            #pragma unroll
            for (int j = 0; j < 8; j++) {
                int n = wn*64 + j*8 + g;
                ldb2(bH[j], st + 20480, 80, n, kb);
                ldb2(bL[j], st + 30720, 80, n, kb);
            }
            #pragma unroll
            for (int i = 0; i < 2; i++)
                #pragma unroll
                for (int j = 0; j < 8; j++) {
                    mma_bf16(acc[i][j], aH[i], bH[j]);
                    mma_bf16(acc[i][j], aH[i], bL[j]);
                    mma_bf16(acc[i][j], aL[i], bH[j]);
                }
        }
        __syncthreads();
    }

    #pragma unroll
    for (int j = 0; j < 8; j++) {
        int c = bn + wn*64 + j*8 + tg*2;
        float b0 = bias[c], b1 = bias[c+1];
        #pragma unroll
        for (int i = 0; i < 2; i++) {
            #pragma unroll
            for (int half = 0; half < 2; half++) {
                int r = bm + wm*32 + i*16 + g + half*8;
                float2 f;
                f.x = acc[i][j][half*2+0] + b0;
                f.y = acc[i][j][half*2+1] + b1;
                *(float2*)&outF[(size_t)r*E_ + c] = f;
            }
        }
    }
}

// ===========================================================================
// 4) exp-scores: E = exp(Q K^T / 8 - 4) per (b,h), stored fp16.
//    Single fp16 product. 128x128 block, K=64 single-shot.
// ===========================================================================
#define SC_SMEM (2*18432)   // 36864
__global__ __launch_bounds__(256) void scores_mma()
{
    char* sm = dynsm;
    const int tid = threadIdx.x, lane = tid & 31, wid = tid >> 5;
    const int wm = wid >> 1, wn = wid & 1;
    const int g = lane >> 2, tg = lane & 3;
    const int bh = blockIdx.z;
    const int bm = blockIdx.y*128, bn = blockIdx.x*128;

    ld_chunk64(sm,           d_Qf + (size_t)bh*S_*D_ + (size_t)bm*D_, D_, 128);
    ld_chunk64(sm + 18432,   d_Kf + (size_t)bh*S_*D_ + (size_t)bn*D_, D_, 128);
    CP_COMMIT(); CP_WAIT0();
    __syncthreads();

    float acc[2][8][4];
    #pragma unroll
    for (int i = 0; i < 2; i++)
        #pragma unroll
        for (int j = 0; j < 8; j++)
            #pragma unroll
            for (int q = 0; q < 4; q++) acc[i][j][q] = 0.f;

    #pragma unroll
    for (int ks = 0; ks < 4; ks++) {
        int kb = ks*32 + tg*4;
        uint32_t aF[2][4], bF[8][2];
        #pragma unroll
        for (int i = 0; i < 2; i++) {
            int r0 = wm*32 + i*16 + g;
            lda4(aF[i], sm, 144, r0, kb);
        }
        #pragma unroll
        for (int j = 0; j < 8; j++) {
            int n = wn*64 + j*8 + g;
            ldb2(bF[j], sm + 18432, 144, n, kb);
        }
        #pragma unroll
        for (int i = 0; i < 2; i++)
            #pragma unroll
            for (int j = 0; j < 8; j++)
                mma_f16(acc[i][j], aF[i], bF[j]);
    }

    __half* outb = d_Es + (size_t)bh*S_*S_;
    #pragma unroll
    for (int i = 0; i < 2; i++)
        #pragma unroll
        for (int j = 0; j < 8; j++) {
            int c = bn + wn*64 + j*8 + tg*2;
            #pragma unroll
            for (int half = 0; half < 2; half++) {
                int r = bm + wm*32 + i*16 + g + half*8;
                float e0 = __expf(acc[i][j][half*2+0] * 0.125f - 4.f);
                float e1 = __expf(acc[i][j][half*2+1] * 0.125f - 4.f);
                *(__half2*)&outb[(size_t)r*S_ + c] = __floats2half2_rn(e0, e1);
            }
        }
}

// ===========================================================================
// 5) fused normalize + head mixing (smem-staged). Block per (b,q).
//    If mix rows are uniform, all mixed planes identical -> plane 0 only.
// ===========================================================================
#define SMX_SMEM ((H_*S_ + 16 + 256)*4)   // 132160
__global__ __launch_bounds__(256) void softmax_mix_kernel()
{
    float* sm   = (float*)dynsm;
    float* inv  = sm + H_*S_;
    float* mixs = inv + 16;
    const int bq = blockIdx.x;
    const int b = bq >> 11, q = bq & (S_-1);
    const int tid = threadIdx.x;
    const int uni = d_uniform;

    const __half* src = d_Es + ((size_t)b*H_)*S_*S_ + (size_t)q*S_;
    for (int i = tid; i < H_*S_/8; i += 256) {
        int h = i >> 8, k8 = i & 255;
        const __half2* p = (const __half2*)(src + (size_t)h*S_*S_ + k8*8);
        float* dst = sm + h*S_ + k8*8;
        #pragma unroll
        for (int u = 0; u < 4; u++) {
            float2 f = __half22float2(p[u]);
            dst[u*2+0] = f.x; dst[u*2+1] = f.y;
        }
    }
    mixs[tid] = d_mixsm[tid & 255];
    __syncthreads();

    int w = tid >> 5, lane = tid & 31;
    #pragma unroll
    for (int hh = 0; hh < 2; hh++) {
        int h = w*2 + hh;
        float* row = sm + h*S_;
        float s = 0.f;
        for (int j = lane; j < S_; j += 32) s += row[j];
        #pragma unroll
        for (int o = 16; o; o >>= 1) s += __shfl_xor_sync(0xFFFFFFFFu, s, o);
        if (lane == 0) inv[h] = 1.f / s;
    }
    __syncthreads();

    size_t obase = ((size_t)b*H_)*S_*S_ + (size_t)q*S_;
    if (uni) {
        for (int k2 = tid; k2 < S_/2; k2 += 256) {
            int k0 = k2*2;
            float o0 = 0.f, o1 = 0.f;
            #pragma unroll
            for (int h = 0; h < H_; h++) {
                float mh = mixs[h];
                o0 = fmaf(mh, sm[h*S_ + k0]     * inv[h], o0);
                o1 = fmaf(mh, sm[h*S_ + k0 + 1] * inv[h], o1);
            }
            *(__half2*)&d_Pf[obase + k0] = __floats2half2_rn(o0, o1);
        }
    } else {
        for (int k2 = tid; k2 < S_/2; k2 += 256) {
            int k0 = k2*2;
            float a0[H_], a1[H_];
            #pragma unroll
            for (int h = 0; h < H_; h++) {
                a0[h] = sm[h*S_ + k0]     * inv[h];
                a1[h] = sm[h*S_ + k0 + 1] * inv[h];
            }
            #pragma unroll
            for (int g = 0; g < H_; g++) {
                float o0 = 0.f, o1 = 0.f;
                #pragma unroll
                for (int h = 0; h < H_; h++) {
                    o0 = fmaf(mixs[g*16 + h], a0[h], o0);
                    o1 = fmaf(mixs[g*16 + h], a1[h], o1);
                }
                size_t idx = obase + (size_t)g*S_*S_ + k0;
                *(__half2*)&d_Pf[idx] = __floats2half2_rn(o0, o1);
            }
        }
    }
}

// ===========================================================================
// 6) ctx = P @ V per (b,g), fp16 single-product. 128x64 block, 8 warps.
//    If d_uniform, all P planes equal -> read plane 0 (L2-resident reuse).
// ===========================================================================
#define CTX_STAGE (10240 + 4608)          // 14848
#define CTX_SMEM  (2*CTX_STAGE)           // 29696
__global__ __launch_bounds__(256) void ctx_mma()
{
    char* sm = dynsm;
    const int tid = threadIdx.x, lane = tid & 31, wid = tid >> 5;
    const int wm = wid >> 1, wn = wid & 1;
    const int g = lane >> 2, tg = lane & 3;
    const int bg = blockIdx.y;
    const int b = bg >> 4, ghead = bg & 15;
    const int bm = blockIdx.x*128;
    const int psel = d_uniform ? (b*H_) : bg;

    const __half* pf = d_Pf + (size_t)psel*S_*S_ + (size_t)bm*S_;
    const __half* vf = d_Vf + (size_t)bg*S_*D_;

    float acc[2][4][4];
    #pragma unroll
    for (int i = 0; i < 2; i++)
        #pragma unroll
        for (int j = 0; j < 4; j++)
            #pragma unroll
            for (int q = 0; q < 4; q++) acc[i][j][q] = 0.f;

    {   // preload chunk 0
        char* st = sm;
        ld_chunk32(st,         pf, S_, 128);
        ld_chunk64(st + 10240, vf, D_, 32);
        CP_COMMIT();
    }
    for (int c = 0; c < 64; c++) {
        if (c < 63) {
            int k0 = (c+1)*32;
            char* st = sm + ((c+1)&1)*CTX_STAGE;
            ld_chunk32(st,         pf + k0, S_, 128);
            ld_chunk64(st + 10240, vf + (size_t)k0*D_, D_, 32);
            CP_COMMIT(); CP_WAIT1();
        } else CP_WAIT0();
        __syncthreads();
        const char* st = sm + (c&1)*CTX_STAGE;
        const char* vF = st + 10240;
        #pragma unroll
        for (int ks = 0; ks < 2; ks++) {
            int kb = ks*32 + tg*4;
            uint32_t aF[2][4], bF[4][2];
            #pragma unroll
            for (int i = 0; i < 2; i++) {
                int r0 = wm*32 + i*16 + g;
                lda4(aF[i], st, 80, r0, kb);
            }
            int krow = ks*16 + tg*2;
            #pragma unroll
            for (int j = 0; j < 4; j++) {
                int n2 = (wn*32 + j*8 + g)*2;
                uint32_t x0, x1, x2, x3;
                x0 = *(const unsigned short*)(vF + (krow  )*144 + n2);
                x1 = *(const unsigned short*)(vF + (krow+1)*144 + n2);
                x2 = *(const unsigned short*)(vF + (krow+8)*144 + n2);
                x3 = *(const unsigned short*)(vF + (krow+9)*144 + n2);
                bF[j][0] = x0 | (x1 << 16);
                bF[j][1] = x2 | (x3 << 16);
            }
            #pragma unroll
            for (int i = 0; i < 2; i++)
                #pragma unroll
                for (int j = 0; j < 4; j++)
                    mma_f16(acc[i][j], aF[i], bF[j]);
        }
        __syncthreads();
    }

    #pragma unroll
    for (int i = 0; i < 2; i++)
        #pragma unroll
        for (int j = 0; j < 4; j++) {
            int d = wn*32 + j*8 + tg*2;
            #pragma unroll
            for (int half = 0; half < 2; half++) {
                int q = bm + wm*32 + i*16 + g + half*8;
                float v0 = acc[i][j][half*2+0];
                float v1 = acc[i][j][half*2+1];
                __nv_bfloat16 h0,l0,h1,l1;
                split2(v0,h0,l0); split2(v1,h1,l1);
                size_t idx = ((size_t)b*S_ + q)*E_ + ghead*D_ + d;
                __nv_bfloat162 ph2; ph2.x=h0; ph2.y=h1;
                __nv_bfloat162 pl2; pl2.x=l0; pl2.y=l1;
                *(__nv_bfloat162*)&d_Ch[idx] = ph2;
                *(__nv_bfloat162*)&d_Cl[idx] = pl2;
            }
        }
}

// ===========================================================================
// kernel_launch
// ===========================================================================
extern "C" void kernel_launch(void* const* d_in, const int* in_sizes, int n_in,
                              void* d_out, int out_size)
{
    (void)in_sizes; (void)n_in; (void)out_size;
    const float* query = (const float*)d_in[0];
    const float* key_  = (const float*)d_in[1];
    const float* value = (const float*)d_in[2];
    const float* Wq = (const float*)d_in[3];
    const float* bq = (const float*)d_in[4];
    const float* Wk = (const float*)d_in[5];
    const float* bk = (const float*)d_in[6];
    const float* Wv = (const float*)d_in[7];
    const float* bv = (const float*)d_in[8];
    const float* hm = (const float*)d_in[9];
    const float* Wo = (const float*)d_in[10];
    const float* bo = (const float*)d_in[11];
    float* out = (float*)d_out;

    cudaFuncSetAttribute(gemm_qkv,           cudaFuncAttributeMaxDynamicSharedMemorySize, PROJ_SMEM);
    cudaFuncSetAttribute(gemm_out,           cudaFuncAttributeMaxDynamicSharedMemorySize, OUT_SMEM);
    cudaFuncSetAttribute(scores_mma,         cudaFuncAttributeMaxDynamicSharedMemorySize, SC_SMEM);
    cudaFuncSetAttribute(softmax_mix_kernel, cudaFuncAttributeMaxDynamicSharedMemorySize, SMX_SMEM);
    cudaFuncSetAttribute(ctx_mma,            cudaFuncAttributeMaxDynamicSharedMemorySize, CTX_SMEM);

    const int n4 = TOK_*E_/4;

    mix_softmax_kernel<<<1, 16>>>(hm);
    split_wt3<<<dim3(32, 32, 3), dim3(32, 8)>>>(Wq, Wk, Wv);
    split_f3<<<dim3(n4/256, 1, 3), 256>>>(query, key_, value, n4);
    gemm_qkv<<<dim3(E_/128, TOK_/128, 3), 256, PROJ_SMEM>>>(bq, bk, bv);

    scores_mma<<<dim3(S_/128, S_/128, BH_), 256, SC_SMEM>>>();   // (16,16,32)
    softmax_mix_kernel<<<B_*S_, 256, SMX_SMEM>>>();              // 4096 blocks
    ctx_mma<<<dim3(S_/128, BH_), 256, CTX_SMEM>>>();             // (16,32)

    split_wt<<<dim3(32, 32), dim3(32, 8)>>>(Wo);
    gemm_out<<<dim3(E_/128, TOK_/128), 256, OUT_SMEM>>>(bo, out);
}